// round 12
// baseline (speedup 1.0000x reference)
#include <cuda_runtime.h>
#include <cuda_fp16.h>
#include <math.h>
#include <float.h>
#include <stdint.h>
#include <limits.h>

#define BB    4
#define LL    2048
#define EE    512
#define HH    8
#define DD    64
#define UU    40
#define NTOP  40
#define BH    32
#define NROWS 8192
#define ACH   8
#define ALT   256
#define AST   32

// ---------------- scratch ----------------
__device__ float g_q[BH*LL*DD];
__device__ float g_k[BH*LL*DD];
__device__ float g_v[BH*LL*DD];
__device__ float g_M[BH*LL];
__device__ int   g_top[BH*NTOP];
__device__ float g_pupd[(size_t)ACH*BH*NTOP*DD];
__device__ float g_pden[ACH*BH*NTOP];
__device__ float g_vmean[BH*DD];
__device__ float g_base[BB*EE];
__device__ unsigned long long g_cand[BH*8*NTOP];

// fp16 split scratch: [which q/k/v][split h/l]
__device__ __half g_sx[3][2][(size_t)NROWS*EE];
__device__ __half g_sw[3][2][EE*EE];

// ---------------- split: fp32 -> fp16 hi/lo ----------------
__device__ __forceinline__ void split2(float x, __half& h, __half& l) {
    h = __float2half_rn(x);
    float r = x - __half2float(h);
    l = __float2half_rn(r);
}

__global__ __launch_bounds__(256) void split_kernel(
    const float* __restrict__ s0, const float* __restrict__ s1, const float* __restrict__ s2,
    int n4, int isW)
{
    int which = blockIdx.y;
    const float* src = (which == 0) ? s0 : (which == 1) ? s1 : s2;
    __half* dh = isW ? g_sw[which][0] : g_sx[which][0];
    __half* dl = isW ? g_sw[which][1] : g_sx[which][1];
    int i = blockIdx.x * 256 + threadIdx.x;
    if (i >= n4) return;
    float4 x = ((const float4*)src)[i];
    __half h[4], l[4];
    split2(x.x, h[0], l[0]);
    split2(x.y, h[1], l[1]);
    split2(x.z, h[2], l[2]);
    split2(x.w, h[3], l[3]);
    ((uint2*)dh)[i] = *(uint2*)h;
    ((uint2*)dl)[i] = *(uint2*)l;
}

// ---------------- mma.sync projection GEMM (16 warps, 32x32 warp tile) ----
#define BM 128
#define BN 128
#define BK 32
#define SROW 40
#define TILE_H (BM * SROW)
#define PROJ_SMEM (2 * 4 * TILE_H * 2)

__device__ __forceinline__ uint32_t smem_u32(const void* p) {
    uint32_t a;
    asm("{ .reg .u64 t; cvta.to.shared.u64 t, %1; cvt.u32.u64 %0, t; }" : "=r"(a) : "l"(p));
    return a;
}
__device__ __forceinline__ void cpa16(uint32_t dst, const void* src) {
    asm volatile("cp.async.cg.shared.global [%0], [%1], 16;" :: "r"(dst), "l"(src));
}
__device__ __forceinline__ void ldsm_x4(uint32_t& r0, uint32_t& r1, uint32_t& r2, uint32_t& r3, uint32_t a) {
    asm volatile("ldmatrix.sync.aligned.m8n8.x4.shared.b16 {%0,%1,%2,%3}, [%4];"
        : "=r"(r0), "=r"(r1), "=r"(r2), "=r"(r3) : "r"(a));
}
__device__ __forceinline__ void ldsm_x2(uint32_t& r0, uint32_t& r1, uint32_t a) {
    asm volatile("ldmatrix.sync.aligned.m8n8.x2.shared.b16 {%0,%1}, [%2];"
        : "=r"(r0), "=r"(r1) : "r"(a));
}
__device__ __forceinline__ void mma16816(float* c, const uint32_t* a, const uint32_t* b) {
    asm volatile("mma.sync.aligned.m16n8k16.row.col.f32.f16.f16.f32 "
        "{%0,%1,%2,%3}, {%4,%5,%6,%7}, {%8,%9}, {%0,%1,%2,%3};"
        : "+f"(c[0]), "+f"(c[1]), "+f"(c[2]), "+f"(c[3])
        : "r"(a[0]), "r"(a[1]), "r"(a[2]), "r"(a[3]), "r"(b[0]), "r"(b[1]));
}

__global__ __launch_bounds__(512) void proj_mma(
    int zbase,
    const float* __restrict__ bq, const float* __restrict__ bk, const float* __restrict__ bv)
{
    extern __shared__ __half dsm[];

    int z = blockIdx.z + zbase;
    int m0 = blockIdx.x * BM;
    int n0 = blockIdx.y * BN;
    int tid = threadIdx.x;
    int lane = tid & 31, wid = tid >> 5;   // 16 warps
    int warp_m = wid & 3;                  // 4 x 32-row strips
    int warp_n = wid >> 2;                 // 4 x 32-col strips

    const int nch = EE / BK;   // 16

    const float* bias = (z == 0) ? bq : (z == 1) ? bk : bv;
    float* out = (z == 0) ? g_q : (z == 1) ? g_k : g_v;

    uint32_t sbase = smem_u32(dsm);

    float acc[2][4][4];
    #pragma unroll
    for (int i = 0; i < 2; i++)
        #pragma unroll
        for (int j = 0; j < 4; j++)
            #pragma unroll
            for (int c = 0; c < 4; c++) acc[i][j][c] = 0.f;

    // fill: 512 threads, 1 x 16B vector per tile per thread
    int vrow = tid >> 2, vcc = tid & 3;

    auto issue_load = [&](int c, int buf) {
        int k0 = c * BK;
        const __half* srcs[4] = {
            g_sx[z][0] + (size_t)m0 * EE + k0,
            g_sx[z][1] + (size_t)m0 * EE + k0,
            g_sw[z][0] + (size_t)n0 * EE + k0,
            g_sw[z][1] + (size_t)n0 * EE + k0
        };
        #pragma unroll
        for (int which = 0; which < 4; which++) {
            uint32_t db = sbase + (uint32_t)(buf * 4 + which) * TILE_H * 2;
            cpa16(db + (vrow * SROW + vcc * 8) * 2, srcs[which] + (size_t)vrow * EE + vcc * 8);
        }
        asm volatile("cp.async.commit_group;" ::: "memory");
    };

    issue_load(0, 0);

    for (int c = 0; c < nch; c++) {
        int buf = c & 1;
        if (c + 1 < nch) {
            issue_load(c + 1, buf ^ 1);
            asm volatile("cp.async.wait_group 1;" ::: "memory");
        } else {
            asm volatile("cp.async.wait_group 0;" ::: "memory");
        }
        __syncthreads();

        uint32_t Ah = sbase + (uint32_t)(buf * 4 + 0) * TILE_H * 2;
        uint32_t Al = sbase + (uint32_t)(buf * 4 + 1) * TILE_H * 2;
        uint32_t Bh = sbase + (uint32_t)(buf * 4 + 2) * TILE_H * 2;
        uint32_t Bl = sbase + (uint32_t)(buf * 4 + 3) * TILE_H * 2;

        #pragma unroll
        for (int ks = 0; ks < 2; ks++) {
            uint32_t bhf[4][2], blf[4][2];
            int khb = ks * 16 + ((lane >> 3) & 1) * 8;
            #pragma unroll
            for (int nt = 0; nt < 4; nt++) {
                int r = warp_n * 32 + nt * 8 + (lane & 7);
                ldsm_x2(bhf[nt][0], bhf[nt][1], Bh + (r * SROW + khb) * 2);
                ldsm_x2(blf[nt][0], blf[nt][1], Bl + (r * SROW + khb) * 2);
            }
            int kha = ks * 16 + (lane >> 4) * 8;
            #pragma unroll
            for (int mt = 0; mt < 2; mt++) {
                int r = warp_m * 32 + mt * 16 + (lane & 15);
                uint32_t ahf[4], alf[4];
                ldsm_x4(ahf[0], ahf[1], ahf[2], ahf[3], Ah + (r * SROW + kha) * 2);
                ldsm_x4(alf[0], alf[1], alf[2], alf[3], Al + (r * SROW + kha) * 2);
                #pragma unroll
                for (int nt = 0; nt < 4; nt++) {
                    mma16816(acc[mt][nt], ahf, bhf[nt]);
                    mma16816(acc[mt][nt], ahf, blf[nt]);
                    mma16816(acc[mt][nt], alf, bhf[nt]);
                }
            }
        }
        __syncthreads();
    }

    int gpr = lane >> 2, tg = lane & 3;
    #pragma unroll
    for (int mt = 0; mt < 2; mt++) {
        #pragma unroll
        for (int nt = 0; nt < 4; nt++) {
            int m = m0 + warp_m * 32 + mt * 16 + gpr;
            int n = n0 + warp_n * 32 + nt * 8 + tg * 2;
            float b0v = bias[n], b1v = bias[n + 1];
            int h = n >> 6, d = n & 63;
            {
                int bb = m >> 11, l = m & 2047;
                float2 o = { acc[mt][nt][0] + b0v, acc[mt][nt][1] + b1v };
                *(float2*)&out[(((size_t)bb * HH + h) * LL + l) * DD + d] = o;
            }
            {
                int m2 = m + 8;
                int bb = m2 >> 11, l = m2 & 2047;
                float2 o = { acc[mt][nt][2] + b0v, acc[mt][nt][3] + b1v };
                *(float2*)&out[(((size_t)bb * HH + h) * LL + l) * DD + d] = o;
            }
        }
    }
}

// ---------------- qk_sample ----------------
__global__ __launch_bounds__(256) void qk_sample_kernel(const int* __restrict__ idxs) {
    __shared__ int sidx[32 * UU];
    int t = threadIdx.x;
    int gw0 = blockIdx.x * 32;
    int bh = gw0 >> 11;
    int lbase = gw0 & 2047;

    #pragma unroll
    for (int i = t; i < 32 * UU; i += 256)
        sidx[i] = idxs[lbase * UU + i];
    __syncthreads();

    int w = t >> 5, lane = t & 31;
    int grp = lane >> 3, lid = lane & 7;
    int lix = w * 4 + grp;
    int l = lbase + lix;

    const float* qrow = g_q + ((size_t)bh * LL + l) * DD;
    float4 q0 = *(const float4*)&qrow[lid * 8];
    float4 q1 = *(const float4*)&qrow[lid * 8 + 4];
    const float* kbase = g_k + (size_t)bh * LL * DD;

    float smax = -FLT_MAX, ssum = 0.f;
    #pragma unroll 2
    for (int s = 0; s < UU; s += 2) {
        int ki0 = sidx[lix * UU + s];
        int ki1 = sidx[lix * UU + s + 1];
        const float* kr0 = &kbase[(size_t)ki0 * DD + lid * 8];
        const float* kr1 = &kbase[(size_t)ki1 * DD + lid * 8];
        float4 a0 = *(const float4*)kr0;
        float4 a1 = *(const float4*)(kr0 + 4);
        float4 b0 = *(const float4*)kr1;
        float4 b1 = *(const float4*)(kr1 + 4);
        float p0 = q0.x*a0.x + q0.y*a0.y + q0.z*a0.z + q0.w*a0.w
                 + q1.x*a1.x + q1.y*a1.y + q1.z*a1.z + q1.w*a1.w;
        float p1 = q0.x*b0.x + q0.y*b0.y + q0.z*b0.z + q0.w*b0.w
                 + q1.x*b1.x + q1.y*b1.y + q1.z*b1.z + q1.w*b1.w;
        #pragma unroll
        for (int off = 4; off; off >>= 1) {
            p0 += __shfl_xor_sync(0xffffffffu, p0, off);
            p1 += __shfl_xor_sync(0xffffffffu, p1, off);
        }
        smax = fmaxf(smax, fmaxf(p0, p1));
        ssum += p0 + p1;
    }
    if (lid == 0) g_M[gw0 + lix] = smax - ssum * (1.0f / LL);
}

// ---------------- topk via bitonic sort ----------------
__device__ __forceinline__ unsigned long long pack_key(float v, int idx) {
    uint32_t s = __float_as_uint(v);
    s = (s & 0x80000000u) ? ~s : (s | 0x80000000u);
    return ((unsigned long long)s << 32) | (unsigned long long)(0xFFFFFFFFu - (uint32_t)idx);
}

__global__ __launch_bounds__(256) void topk1_kernel() {
    __shared__ unsigned long long keys[256];
    int bh = blockIdx.x, ch = blockIdx.y, t = threadIdx.x;
    int gidx = ch * 256 + t;
    keys[t] = pack_key(g_M[bh * LL + gidx], gidx);
    __syncthreads();
    for (int k = 2; k <= 256; k <<= 1) {
        for (int j = k >> 1; j > 0; j >>= 1) {
            int ixj = t ^ j;
            unsigned long long a = keys[t], b = keys[ixj];
            bool desc = ((t & k) == 0);
            unsigned long long mx = (a > b) ? a : b;
            unsigned long long mn = (a > b) ? b : a;
            unsigned long long nv = (((t < ixj) == desc) ? mx : mn);
            __syncthreads();
            keys[t] = nv;
            __syncthreads();
        }
    }
    if (t < NTOP) g_cand[(bh * 8 + ch) * NTOP + t] = keys[t];
}

__global__ __launch_bounds__(512) void topk2_kernel() {
    __shared__ unsigned long long keys[512];
    int bh = blockIdx.x, t = threadIdx.x;
    keys[t] = (t < 8 * NTOP) ? g_cand[bh * 8 * NTOP + t] : 0ull;
    __syncthreads();
    for (int k = 2; k <= 512; k <<= 1) {
        for (int j = k >> 1; j > 0; j >>= 1) {
            int ixj = t ^ j;
            unsigned long long a = keys[t], b = keys[ixj];
            bool desc = ((t & k) == 0);
            unsigned long long mx = (a > b) ? a : b;
            unsigned long long mn = (a > b) ? b : a;
            unsigned long long nv = (((t < ixj) == desc) ? mx : mn);
            __syncthreads();
            keys[t] = nv;
            __syncthreads();
        }
    }
    if (t < NTOP)
        g_top[bh * NTOP + t] = (int)(0xFFFFFFFFu - (uint32_t)(keys[t] & 0xFFFFFFFFu));
}

// ---------------- fused scores+exp+den+upd ----------------
__global__ __launch_bounds__(256) void attn_fused() {
    __shared__ float qs[NTOP * DD];
    __shared__ float kst[DD][AST + 1];
    __shared__ float vs[AST * DD];
    __shared__ float es[NTOP][AST];

    int bh = blockIdx.x, ch = blockIdx.y;
    int t = threadIdx.x;
    int lane = t & 31, w = t >> 5;
    int d = t & 63, gq = t >> 6;

    for (int i = t; i < NTOP * DD; i += 256) {
        int u = i >> 6, dd = i & 63;
        int l = g_top[bh * NTOP + u];
        qs[i] = g_q[((size_t)bh * LL + l) * DD + dd];
    }

    float den_acc[5] = {0.f, 0.f, 0.f, 0.f, 0.f};
    float upd_acc[10] = {0.f,0.f,0.f,0.f,0.f,0.f,0.f,0.f,0.f,0.f};

    for (int st = 0; st < ALT / AST; st++) {
        int l0 = ch * ALT + st * AST;
        __syncthreads();
        for (int i = t; i < AST * DD; i += 256) {
            int ln = i >> 6, dd = i & 63;
            kst[dd][ln] = g_k[((size_t)bh * LL + l0 + ln) * DD + dd];
        }
        for (int i = t; i < AST * DD; i += 256)
            vs[i] = g_v[((size_t)bh * LL + l0) * DD + i];
        __syncthreads();

        float sc[5] = {0.f, 0.f, 0.f, 0.f, 0.f};
        #pragma unroll 8
        for (int kk = 0; kk < DD; kk++) {
            float kv = kst[kk][lane];
            #pragma unroll
            for (int g = 0; g < 5; g++)
                sc[g] += qs[(g * 8 + w) * DD + kk] * kv;
        }
        #pragma unroll
        for (int g = 0; g < 5; g++) {
            float e = expf(sc[g]);
            es[g * 8 + w][lane] = e;
            den_acc[g] += e;
        }
        __syncthreads();

        #pragma unroll 8
        for (int ln = 0; ln < AST; ln++) {
            float vv = vs[ln * DD + d];
            #pragma unroll
            for (int j = 0; j < 10; j++)
                upd_acc[j] += es[gq * 10 + j][ln] * vv;
        }
    }

    #pragma unroll
    for (int j = 0; j < 10; j++) {
        int u = gq * 10 + j;
        g_pupd[(((size_t)ch * BH + bh) * NTOP + u) * DD + d] = upd_acc[j];
    }
    #pragma unroll
    for (int g = 0; g < 5; g++) {
        float v = den_acc[g];
        #pragma unroll
        for (int off = 16; off; off >>= 1) v += __shfl_xor_sync(0xffffffffu, v, off);
        if (lane == 0) g_pden[(ch * BH + bh) * NTOP + g * 8 + w] = v;
    }
}

__global__ __launch_bounds__(256) void vmean_kernel() {
    __shared__ float sm[256];
    int bh = blockIdx.x, t = threadIdx.x;
    int d = t & 63, p = t >> 6;
    float s = 0.f;
    for (int l = p; l < LL; l += 4) s += g_v[((size_t)bh * LL + l) * DD + d];
    sm[t] = s; __syncthreads();
    if (t < 128) sm[t] += sm[t + 128];
    __syncthreads();
    if (t < 64) g_vmean[bh * DD + t] = (sm[t] + sm[t + 64]) * (1.0f / LL);
}

__global__ __launch_bounds__(128) void base_kernel(const float* __restrict__ Wo,
                                                   const float* __restrict__ bo) {
    __shared__ float cm[EE];
    int b = blockIdx.x, jc = blockIdx.y, t = threadIdx.x;
    for (int i = t; i < EE; i += 128) cm[i] = g_vmean[b * EE + i];
    __syncthreads();
    int j = jc * 128 + t;
    float acc = bo[j];
    const float* wrow = Wo + (size_t)j * EE;
    for (int e = 0; e < EE; e += 4) {
        float4 w = *(const float4*)&wrow[e];
        acc += cm[e] * w.x + cm[e+1] * w.y + cm[e+2] * w.z + cm[e+3] * w.w;
    }
    g_base[b * EE + j] = acc;
}

__global__ __launch_bounds__(256) void fill_kernel(float4* __restrict__ out4) {
    int i = blockIdx.x * 256 + threadIdx.x;
    int b  = i >> 18;
    int j4 = i & 127;
    out4[i] = *(const float4*)&g_base[b * EE + j4 * 4];
}

// ---------------- fused updreduce + sparse row update ----------------
__global__ __launch_bounds__(512) void update_kernel(const float* __restrict__ Wo,
                                                     float* __restrict__ out) {
    __shared__ float del[DD];
    int r = blockIdx.x;
    int bh = r / NTOP, u = r - bh * NTOP;
    int b = bh >> 3, h = bh & 7;
    int t = threadIdx.x;
    if (t < DD) {
        float s = 0.f, den = 0.f;
        #pragma unroll
        for (int c = 0; c < ACH; c++) {
            s   += g_pupd[(((size_t)c * BH + bh) * NTOP + u) * DD + t];
            den += g_pden[(c * BH + bh) * NTOP + u];
        }
        del[t] = s / den - g_vmean[bh * DD + t];
    }
    __syncthreads();
    int l = g_top[r];
    const float* wrow = Wo + (size_t)t * EE + h * DD;
    float acc = 0.f;
    #pragma unroll
    for (int dd = 0; dd < DD; dd += 4) {
        float4 w = *(const float4*)&wrow[dd];
        acc += del[dd] * w.x + del[dd+1] * w.y + del[dd+2] * w.z + del[dd+3] * w.w;
    }
    atomicAdd(&out[((size_t)b * LL + l) * EE + t], acc);
}

extern "C" void kernel_launch(void* const* d_in, const int* in_sizes, int n_in,
                              void* d_out, int out_size) {
    const float* query = (const float*)d_in[0];
    const float* key   = (const float*)d_in[1];
    const float* value = (const float*)d_in[2];
    const int*   idxs  = (const int*)d_in[3];
    const float* Wq = (const float*)d_in[4];
    const float* bq = (const float*)d_in[5];
    const float* Wk = (const float*)d_in[6];
    const float* bk = (const float*)d_in[7];
    const float* Wv = (const float*)d_in[8];
    const float* bv = (const float*)d_in[9];
    const float* Wo = (const float*)d_in[10];
    const float* bo = (const float*)d_in[11];
    float* out = (float*)d_out;

    static cudaStream_t s2 = nullptr;
    static cudaEvent_t eSplit = nullptr, eV = nullptr, eFill = nullptr;
    if (s2 == nullptr) {
        cudaStreamCreateWithFlags(&s2, cudaStreamNonBlocking);
        cudaEventCreateWithFlags(&eSplit, cudaEventDisableTiming);
        cudaEventCreateWithFlags(&eV, cudaEventDisableTiming);
        cudaEventCreateWithFlags(&eFill, cudaEventDisableTiming);
    }

    cudaFuncSetAttribute(proj_mma, cudaFuncAttributeMaxDynamicSharedMemorySize, PROJ_SMEM);

    // ---- main stream: splits, then q,k projection ----
    split_kernel<<<dim3(NROWS * EE / 4 / 256, 3), 256>>>(query, key, value, NROWS * EE / 4, 0);
    split_kernel<<<dim3(EE * EE / 4 / 256, 3), 256>>>(Wq, Wk, Wv, EE * EE / 4, 1);
    cudaEventRecord(eSplit, 0);

    proj_mma<<<dim3(NROWS / BM, EE / BN, 2), 512, PROJ_SMEM>>>(0, bq, bk, bv);   // q, k

    // ---- side stream: v projection, vmean, base, fill ----
    cudaStreamWaitEvent(s2, eSplit, 0);
    proj_mma<<<dim3(NROWS / BM, EE / BN, 1), 512, PROJ_SMEM, s2>>>(2, bq, bk, bv);  // v
    cudaEventRecord(eV, s2);
    vmean_kernel<<<BH, 256, 0, s2>>>();
    base_kernel<<<dim3(BB, 4), 128, 0, s2>>>(Wo, bo);
    fill_kernel<<<4096, 256, 0, s2>>>((float4*)out);
    cudaEventRecord(eFill, s2);

    // ---- main stream: qk -> topk -> attn -> update ----
    qk_sample_kernel<<<BH * LL / 32, 256>>>(idxs);
    topk1_kernel<<<dim3(BH, 8), 256>>>();
    topk2_kernel<<<BH, 512>>>();
    cudaStreamWaitEvent(0, eV, 0);
    attn_fused<<<dim3(BH, ACH), 256>>>();
    cudaStreamWaitEvent(0, eFill, 0);
    update_kernel<<<BH * NTOP, 512>>>(Wo, out);
}

// round 13
// speedup vs baseline: 1.0708x; 1.0708x over previous
#include <cuda_runtime.h>
#include <cuda_fp16.h>
#include <math.h>
#include <float.h>
#include <stdint.h>
#include <limits.h>

#define BB    4
#define LL    2048
#define EE    512
#define HH    8
#define DD    64
#define UU    40
#define NTOP  40
#define BH    32
#define NROWS 8192
#define ACH   8
#define ALT   256
#define AST   32

// ---------------- scratch ----------------
__device__ float g_q[BH*LL*DD];
__device__ float g_k[BH*LL*DD];
__device__ float g_v[BH*LL*DD];
__device__ float g_M[BH*LL];
__device__ int   g_top[BH*NTOP];
__device__ float g_pupd[(size_t)ACH*BH*NTOP*DD];
__device__ float g_pden[ACH*BH*NTOP];
__device__ float g_vmean[BH*DD];
__device__ float g_base[BB*EE];
__device__ unsigned long long g_cand[BH*8*NTOP];

// fp16 split scratch: [which q/k/v][split h/l]
__device__ __half g_sx[3][2][(size_t)NROWS*EE];
__device__ __half g_sw[3][2][EE*EE];

// ---------------- split: fp32 -> fp16 hi/lo ----------------
__device__ __forceinline__ void split2(float x, __half& h, __half& l) {
    h = __float2half_rn(x);
    float r = x - __half2float(h);
    l = __float2half_rn(r);
}

__global__ __launch_bounds__(256) void split_kernel(
    const float* __restrict__ s0, const float* __restrict__ s1, const float* __restrict__ s2,
    int n4, int isW)
{
    int which = blockIdx.y;
    const float* src = (which == 0) ? s0 : (which == 1) ? s1 : s2;
    __half* dh = isW ? g_sw[which][0] : g_sx[which][0];
    __half* dl = isW ? g_sw[which][1] : g_sx[which][1];
    int i = blockIdx.x * 256 + threadIdx.x;
    if (i >= n4) return;
    float4 x = ((const float4*)src)[i];
    __half h[4], l[4];
    split2(x.x, h[0], l[0]);
    split2(x.y, h[1], l[1]);
    split2(x.z, h[2], l[2]);
    split2(x.w, h[3], l[3]);
    ((uint2*)dh)[i] = *(uint2*)h;
    ((uint2*)dl)[i] = *(uint2*)l;
}

// ---------------- mma.sync projection GEMM (16 warps, 2 CTA/SM forced) ----
#define BM 128
#define BN 128
#define BK 32
#define SROW 40
#define TILE_H (BM * SROW)
#define PROJ_SMEM (2 * 4 * TILE_H * 2)

__device__ __forceinline__ uint32_t smem_u32(const void* p) {
    uint32_t a;
    asm("{ .reg .u64 t; cvta.to.shared.u64 t, %1; cvt.u32.u64 %0, t; }" : "=r"(a) : "l"(p));
    return a;
}
__device__ __forceinline__ void cpa16(uint32_t dst, const void* src) {
    asm volatile("cp.async.cg.shared.global [%0], [%1], 16;" :: "r"(dst), "l"(src));
}
__device__ __forceinline__ void ldsm_x4(uint32_t& r0, uint32_t& r1, uint32_t& r2, uint32_t& r3, uint32_t a) {
    asm volatile("ldmatrix.sync.aligned.m8n8.x4.shared.b16 {%0,%1,%2,%3}, [%4];"
        : "=r"(r0), "=r"(r1), "=r"(r2), "=r"(r3) : "r"(a));
}
__device__ __forceinline__ void ldsm_x2(uint32_t& r0, uint32_t& r1, uint32_t a) {
    asm volatile("ldmatrix.sync.aligned.m8n8.x2.shared.b16 {%0,%1}, [%2];"
        : "=r"(r0), "=r"(r1) : "r"(a));
}
__device__ __forceinline__ void mma16816(float* c, const uint32_t* a, const uint32_t* b) {
    asm volatile("mma.sync.aligned.m16n8k16.row.col.f32.f16.f16.f32 "
        "{%0,%1,%2,%3}, {%4,%5,%6,%7}, {%8,%9}, {%0,%1,%2,%3};"
        : "+f"(c[0]), "+f"(c[1]), "+f"(c[2]), "+f"(c[3])
        : "r"(a[0]), "r"(a[1]), "r"(a[2]), "r"(a[3]), "r"(b[0]), "r"(b[1]));
}

__global__ __launch_bounds__(512, 2) void proj_mma(
    int zbase,
    const float* __restrict__ bq, const float* __restrict__ bk, const float* __restrict__ bv)
{
    extern __shared__ __half dsm[];

    int z = blockIdx.z + zbase;
    int m0 = blockIdx.x * BM;
    int n0 = blockIdx.y * BN;
    int tid = threadIdx.x;
    int lane = tid & 31, wid = tid >> 5;   // 16 warps
    int warp_m = wid & 3;                  // 4 x 32-row strips
    int warp_n = wid >> 2;                 // 4 x 32-col strips

    const int nch = EE / BK;   // 16

    const float* bias = (z == 0) ? bq : (z == 1) ? bk : bv;
    float* out = (z == 0) ? g_q : (z == 1) ? g_k : g_v;

    uint32_t sbase = smem_u32(dsm);

    float acc[2][4][4];
    #pragma unroll
    for (int i = 0; i < 2; i++)
        #pragma unroll
        for (int j = 0; j < 4; j++)
            #pragma unroll
            for (int c = 0; c < 4; c++) acc[i][j][c] = 0.f;

    // fill: 512 threads, 1 x 16B vector per tile per thread
    int vrow = tid >> 2, vcc = tid & 3;

    auto issue_load = [&](int c, int buf) {
        int k0 = c * BK;
        const __half* srcs[4] = {
            g_sx[z][0] + (size_t)m0 * EE + k0,
            g_sx[z][1] + (size_t)m0 * EE + k0,
            g_sw[z][0] + (size_t)n0 * EE + k0,
            g_sw[z][1] + (size_t)n0 * EE + k0
        };
        #pragma unroll
        for (int which = 0; which < 4; which++) {
            uint32_t db = sbase + (uint32_t)(buf * 4 + which) * TILE_H * 2;
            cpa16(db + (vrow * SROW + vcc * 8) * 2, srcs[which] + (size_t)vrow * EE + vcc * 8);
        }
        asm volatile("cp.async.commit_group;" ::: "memory");
    };

    issue_load(0, 0);

    for (int c = 0; c < nch; c++) {
        int buf = c & 1;
        if (c + 1 < nch) {
            issue_load(c + 1, buf ^ 1);
            asm volatile("cp.async.wait_group 1;" ::: "memory");
        } else {
            asm volatile("cp.async.wait_group 0;" ::: "memory");
        }
        __syncthreads();

        uint32_t Ah = sbase + (uint32_t)(buf * 4 + 0) * TILE_H * 2;
        uint32_t Al = sbase + (uint32_t)(buf * 4 + 1) * TILE_H * 2;
        uint32_t Bh = sbase + (uint32_t)(buf * 4 + 2) * TILE_H * 2;
        uint32_t Bl = sbase + (uint32_t)(buf * 4 + 3) * TILE_H * 2;

        #pragma unroll
        for (int ks = 0; ks < 2; ks++) {
            uint32_t bhf[4][2], blf[4][2];
            int khb = ks * 16 + ((lane >> 3) & 1) * 8;
            #pragma unroll
            for (int nt = 0; nt < 4; nt++) {
                int r = warp_n * 32 + nt * 8 + (lane & 7);
                ldsm_x2(bhf[nt][0], bhf[nt][1], Bh + (r * SROW + khb) * 2);
                ldsm_x2(blf[nt][0], blf[nt][1], Bl + (r * SROW + khb) * 2);
            }
            int kha = ks * 16 + (lane >> 4) * 8;
            #pragma unroll
            for (int mt = 0; mt < 2; mt++) {
                int r = warp_m * 32 + mt * 16 + (lane & 15);
                uint32_t ahf[4], alf[4];
                ldsm_x4(ahf[0], ahf[1], ahf[2], ahf[3], Ah + (r * SROW + kha) * 2);
                ldsm_x4(alf[0], alf[1], alf[2], alf[3], Al + (r * SROW + kha) * 2);
                #pragma unroll
                for (int nt = 0; nt < 4; nt++) {
                    mma16816(acc[mt][nt], ahf, bhf[nt]);
                    mma16816(acc[mt][nt], ahf, blf[nt]);
                    mma16816(acc[mt][nt], alf, bhf[nt]);
                }
            }
        }
        __syncthreads();
    }

    int gpr = lane >> 2, tg = lane & 3;
    #pragma unroll
    for (int mt = 0; mt < 2; mt++) {
        #pragma unroll
        for (int nt = 0; nt < 4; nt++) {
            int m = m0 + warp_m * 32 + mt * 16 + gpr;
            int n = n0 + warp_n * 32 + nt * 8 + tg * 2;
            float b0v = bias[n], b1v = bias[n + 1];
            int h = n >> 6, d = n & 63;
            {
                int bb = m >> 11, l = m & 2047;
                float2 o = { acc[mt][nt][0] + b0v, acc[mt][nt][1] + b1v };
                *(float2*)&out[(((size_t)bb * HH + h) * LL + l) * DD + d] = o;
            }
            {
                int m2 = m + 8;
                int bb = m2 >> 11, l = m2 & 2047;
                float2 o = { acc[mt][nt][2] + b0v, acc[mt][nt][3] + b1v };
                *(float2*)&out[(((size_t)bb * HH + h) * LL + l) * DD + d] = o;
            }
        }
    }
}

// ---------------- qk_sample ----------------
__global__ __launch_bounds__(256) void qk_sample_kernel(const int* __restrict__ idxs) {
    __shared__ int sidx[32 * UU];
    int t = threadIdx.x;
    int gw0 = blockIdx.x * 32;
    int bh = gw0 >> 11;
    int lbase = gw0 & 2047;

    #pragma unroll
    for (int i = t; i < 32 * UU; i += 256)
        sidx[i] = idxs[lbase * UU + i];
    __syncthreads();

    int w = t >> 5, lane = t & 31;
    int grp = lane >> 3, lid = lane & 7;
    int lix = w * 4 + grp;
    int l = lbase + lix;

    const float* qrow = g_q + ((size_t)bh * LL + l) * DD;
    float4 q0 = *(const float4*)&qrow[lid * 8];
    float4 q1 = *(const float4*)&qrow[lid * 8 + 4];
    const float* kbase = g_k + (size_t)bh * LL * DD;

    float smax = -FLT_MAX, ssum = 0.f;
    #pragma unroll 2
    for (int s = 0; s < UU; s += 2) {
        int ki0 = sidx[lix * UU + s];
        int ki1 = sidx[lix * UU + s + 1];
        const float* kr0 = &kbase[(size_t)ki0 * DD + lid * 8];
        const float* kr1 = &kbase[(size_t)ki1 * DD + lid * 8];
        float4 a0 = *(const float4*)kr0;
        float4 a1 = *(const float4*)(kr0 + 4);
        float4 b0 = *(const float4*)kr1;
        float4 b1 = *(const float4*)(kr1 + 4);
        float p0 = q0.x*a0.x + q0.y*a0.y + q0.z*a0.z + q0.w*a0.w
                 + q1.x*a1.x + q1.y*a1.y + q1.z*a1.z + q1.w*a1.w;
        float p1 = q0.x*b0.x + q0.y*b0.y + q0.z*b0.z + q0.w*b0.w
                 + q1.x*b1.x + q1.y*b1.y + q1.z*b1.z + q1.w*b1.w;
        #pragma unroll
        for (int off = 4; off; off >>= 1) {
            p0 += __shfl_xor_sync(0xffffffffu, p0, off);
            p1 += __shfl_xor_sync(0xffffffffu, p1, off);
        }
        smax = fmaxf(smax, fmaxf(p0, p1));
        ssum += p0 + p1;
    }
    if (lid == 0) g_M[gw0 + lix] = smax - ssum * (1.0f / LL);
}

// ---------------- topk via bitonic sort ----------------
__device__ __forceinline__ unsigned long long pack_key(float v, int idx) {
    uint32_t s = __float_as_uint(v);
    s = (s & 0x80000000u) ? ~s : (s | 0x80000000u);
    return ((unsigned long long)s << 32) | (unsigned long long)(0xFFFFFFFFu - (uint32_t)idx);
}

__global__ __launch_bounds__(256) void topk1_kernel() {
    __shared__ unsigned long long keys[256];
    int bh = blockIdx.x, ch = blockIdx.y, t = threadIdx.x;
    int gidx = ch * 256 + t;
    keys[t] = pack_key(g_M[bh * LL + gidx], gidx);
    __syncthreads();
    for (int k = 2; k <= 256; k <<= 1) {
        for (int j = k >> 1; j > 0; j >>= 1) {
            int ixj = t ^ j;
            unsigned long long a = keys[t], b = keys[ixj];
            bool desc = ((t & k) == 0);
            unsigned long long mx = (a > b) ? a : b;
            unsigned long long mn = (a > b) ? b : a;
            unsigned long long nv = (((t < ixj) == desc) ? mx : mn);
            __syncthreads();
            keys[t] = nv;
            __syncthreads();
        }
    }
    if (t < NTOP) g_cand[(bh * 8 + ch) * NTOP + t] = keys[t];
}

__global__ __launch_bounds__(512) void topk2_kernel() {
    __shared__ unsigned long long keys[512];
    int bh = blockIdx.x, t = threadIdx.x;
    keys[t] = (t < 8 * NTOP) ? g_cand[bh * 8 * NTOP + t] : 0ull;
    __syncthreads();
    for (int k = 2; k <= 512; k <<= 1) {
        for (int j = k >> 1; j > 0; j >>= 1) {
            int ixj = t ^ j;
            unsigned long long a = keys[t], b = keys[ixj];
            bool desc = ((t & k) == 0);
            unsigned long long mx = (a > b) ? a : b;
            unsigned long long mn = (a > b) ? b : a;
            unsigned long long nv = (((t < ixj) == desc) ? mx : mn);
            __syncthreads();
            keys[t] = nv;
            __syncthreads();
        }
    }
    if (t < NTOP)
        g_top[bh * NTOP + t] = (int)(0xFFFFFFFFu - (uint32_t)(keys[t] & 0xFFFFFFFFu));
}

// ---------------- fused scores+exp+den+upd ----------------
__global__ __launch_bounds__(256) void attn_fused() {
    __shared__ float qs[NTOP * DD];
    __shared__ float kst[DD][AST + 1];
    __shared__ float vs[AST * DD];
    __shared__ float es[NTOP][AST];

    int bh = blockIdx.x, ch = blockIdx.y;
    int t = threadIdx.x;
    int lane = t & 31, w = t >> 5;
    int d = t & 63, gq = t >> 6;

    for (int i = t; i < NTOP * DD; i += 256) {
        int u = i >> 6, dd = i & 63;
        int l = g_top[bh * NTOP + u];
        qs[i] = g_q[((size_t)bh * LL + l) * DD + dd];
    }

    float den_acc[5] = {0.f, 0.f, 0.f, 0.f, 0.f};
    float upd_acc[10] = {0.f,0.f,0.f,0.f,0.f,0.f,0.f,0.f,0.f,0.f};

    for (int st = 0; st < ALT / AST; st++) {
        int l0 = ch * ALT + st * AST;
        __syncthreads();
        for (int i = t; i < AST * DD; i += 256) {
            int ln = i >> 6, dd = i & 63;
            kst[dd][ln] = g_k[((size_t)bh * LL + l0 + ln) * DD + dd];
        }
        for (int i = t; i < AST * DD; i += 256)
            vs[i] = g_v[((size_t)bh * LL + l0) * DD + i];
        __syncthreads();

        float sc[5] = {0.f, 0.f, 0.f, 0.f, 0.f};
        #pragma unroll 8
        for (int kk = 0; kk < DD; kk++) {
            float kv = kst[kk][lane];
            #pragma unroll
            for (int g = 0; g < 5; g++)
                sc[g] += qs[(g * 8 + w) * DD + kk] * kv;
        }
        #pragma unroll
        for (int g = 0; g < 5; g++) {
            float e = expf(sc[g]);
            es[g * 8 + w][lane] = e;
            den_acc[g] += e;
        }
        __syncthreads();

        #pragma unroll 8
        for (int ln = 0; ln < AST; ln++) {
            float vv = vs[ln * DD + d];
            #pragma unroll
            for (int j = 0; j < 10; j++)
                upd_acc[j] += es[gq * 10 + j][ln] * vv;
        }
    }

    #pragma unroll
    for (int j = 0; j < 10; j++) {
        int u = gq * 10 + j;
        g_pupd[(((size_t)ch * BH + bh) * NTOP + u) * DD + d] = upd_acc[j];
    }
    #pragma unroll
    for (int g = 0; g < 5; g++) {
        float v = den_acc[g];
        #pragma unroll
        for (int off = 16; off; off >>= 1) v += __shfl_xor_sync(0xffffffffu, v, off);
        if (lane == 0) g_pden[(ch * BH + bh) * NTOP + g * 8 + w] = v;
    }
}

__global__ __launch_bounds__(256) void vmean_kernel() {
    __shared__ float sm[256];
    int bh = blockIdx.x, t = threadIdx.x;
    int d = t & 63, p = t >> 6;
    float s = 0.f;
    for (int l = p; l < LL; l += 4) s += g_v[((size_t)bh * LL + l) * DD + d];
    sm[t] = s; __syncthreads();
    if (t < 128) sm[t] += sm[t + 128];
    __syncthreads();
    if (t < 64) g_vmean[bh * DD + t] = (sm[t] + sm[t + 64]) * (1.0f / LL);
}

__global__ __launch_bounds__(128) void base_kernel(const float* __restrict__ Wo,
                                                   const float* __restrict__ bo) {
    __shared__ float cm[EE];
    int b = blockIdx.x, jc = blockIdx.y, t = threadIdx.x;
    for (int i = t; i < EE; i += 128) cm[i] = g_vmean[b * EE + i];
    __syncthreads();
    int j = jc * 128 + t;
    float acc = bo[j];
    const float* wrow = Wo + (size_t)j * EE;
    for (int e = 0; e < EE; e += 4) {
        float4 w = *(const float4*)&wrow[e];
        acc += cm[e] * w.x + cm[e+1] * w.y + cm[e+2] * w.z + cm[e+3] * w.w;
    }
    g_base[b * EE + j] = acc;
}

__global__ __launch_bounds__(256) void fill_kernel(float4* __restrict__ out4) {
    int i = blockIdx.x * 256 + threadIdx.x;
    int b  = i >> 18;
    int j4 = i & 127;
    out4[i] = *(const float4*)&g_base[b * EE + j4 * 4];
}

// ---------------- fused updreduce + sparse row update ----------------
__global__ __launch_bounds__(512) void update_kernel(const float* __restrict__ Wo,
                                                     float* __restrict__ out) {
    __shared__ float del[DD];
    int r = blockIdx.x;
    int bh = r / NTOP, u = r - bh * NTOP;
    int b = bh >> 3, h = bh & 7;
    int t = threadIdx.x;
    if (t < DD) {
        float s = 0.f, den = 0.f;
        #pragma unroll
        for (int c = 0; c < ACH; c++) {
            s   += g_pupd[(((size_t)c * BH + bh) * NTOP + u) * DD + t];
            den += g_pden[(c * BH + bh) * NTOP + u];
        }
        del[t] = s / den - g_vmean[bh * DD + t];
    }
    __syncthreads();
    int l = g_top[r];
    const float* wrow = Wo + (size_t)t * EE + h * DD;
    float acc = 0.f;
    #pragma unroll
    for (int dd = 0; dd < DD; dd += 4) {
        float4 w = *(const float4*)&wrow[dd];
        acc += del[dd] * w.x + del[dd+1] * w.y + del[dd+2] * w.z + del[dd+3] * w.w;
    }
    atomicAdd(&out[((size_t)b * LL + l) * EE + t], acc);
}

extern "C" void kernel_launch(void* const* d_in, const int* in_sizes, int n_in,
                              void* d_out, int out_size) {
    const float* query = (const float*)d_in[0];
    const float* key   = (const float*)d_in[1];
    const float* value = (const float*)d_in[2];
    const int*   idxs  = (const int*)d_in[3];
    const float* Wq = (const float*)d_in[4];
    const float* bq = (const float*)d_in[5];
    const float* Wk = (const float*)d_in[6];
    const float* bk = (const float*)d_in[7];
    const float* Wv = (const float*)d_in[8];
    const float* bv = (const float*)d_in[9];
    const float* Wo = (const float*)d_in[10];
    const float* bo = (const float*)d_in[11];
    float* out = (float*)d_out;

    static cudaStream_t s2 = nullptr;
    static cudaEvent_t eSplit = nullptr, eV = nullptr, eFill = nullptr;
    if (s2 == nullptr) {
        cudaStreamCreateWithFlags(&s2, cudaStreamNonBlocking);
        cudaEventCreateWithFlags(&eSplit, cudaEventDisableTiming);
        cudaEventCreateWithFlags(&eV, cudaEventDisableTiming);
        cudaEventCreateWithFlags(&eFill, cudaEventDisableTiming);
    }

    cudaFuncSetAttribute(proj_mma, cudaFuncAttributeMaxDynamicSharedMemorySize, PROJ_SMEM);

    // ---- main stream: splits, then q,k projection ----
    split_kernel<<<dim3(NROWS * EE / 4 / 256, 3), 256>>>(query, key, value, NROWS * EE / 4, 0);
    split_kernel<<<dim3(EE * EE / 4 / 256, 3), 256>>>(Wq, Wk, Wv, EE * EE / 4, 1);
    cudaEventRecord(eSplit, 0);

    proj_mma<<<dim3(NROWS / BM, EE / BN, 2), 512, PROJ_SMEM>>>(0, bq, bk, bv);   // q, k

    // ---- side stream: v projection, vmean, base, fill ----
    cudaStreamWaitEvent(s2, eSplit, 0);
    proj_mma<<<dim3(NROWS / BM, EE / BN, 1), 512, PROJ_SMEM, s2>>>(2, bq, bk, bv);  // v
    cudaEventRecord(eV, s2);
    vmean_kernel<<<BH, 256, 0, s2>>>();
    base_kernel<<<dim3(BB, 4), 128, 0, s2>>>(Wo, bo);
    fill_kernel<<<4096, 256, 0, s2>>>((float4*)out);
    cudaEventRecord(eFill, s2);

    // ---- main stream: qk -> topk -> attn -> update ----
    qk_sample_kernel<<<BH * LL / 32, 256>>>(idxs);
    topk1_kernel<<<dim3(BH, 8), 256>>>();
    topk2_kernel<<<BH, 512>>>();
    cudaStreamWaitEvent(0, eV, 0);
    attn_fused<<<dim3(BH, ACH), 256>>>();
    cudaStreamWaitEvent(0, eFill, 0);
    update_kernel<<<BH * NTOP, 512>>>(Wo, out);
}

// round 14
// speedup vs baseline: 1.1063x; 1.0331x over previous
#include <cuda_runtime.h>
#include <cuda_fp16.h>
#include <math.h>
#include <float.h>
#include <stdint.h>
#include <limits.h>

#define BB    4
#define LL    2048
#define EE    512
#define HH    8
#define DD    64
#define UU    40
#define NTOP  40
#define BH    32
#define NROWS 8192
#define ACH   8
#define ALT   256
#define AST   32

// ---------------- scratch ----------------
__device__ float g_q[BH*LL*DD];
__device__ float g_k[BH*LL*DD];
__device__ float g_v[BH*LL*DD];
__device__ float g_M[BH*LL];
__device__ int   g_top[BH*NTOP];
__device__ float g_pupd[(size_t)ACH*BH*NTOP*DD];
__device__ float g_pden[ACH*BH*NTOP];
__device__ float g_vmean[BH*DD];
__device__ float g_base[BB*EE];
__device__ unsigned long long g_cand[BH*8*NTOP];

// fp16 split scratch: [which q/k/v][split h/l]
__device__ __half g_sx[3][2][(size_t)NROWS*EE];
__device__ __half g_sw[3][2][EE*EE];

// ---------------- split: fp32 -> fp16 hi/lo ----------------
__device__ __forceinline__ void split2(float x, __half& h, __half& l) {
    h = __float2half_rn(x);
    float r = x - __half2float(h);
    l = __float2half_rn(r);
}

// which = blockIdx.y + which0 selects tensor; isW selects weight vs activation dest
__global__ __launch_bounds__(256) void split_kernel(
    const float* __restrict__ s0, const float* __restrict__ s1, const float* __restrict__ s2,
    int n4, int isW, int which0)
{
    int which = blockIdx.y + which0;
    const float* src = (which == 0) ? s0 : (which == 1) ? s1 : s2;
    __half* dh = isW ? g_sw[which][0] : g_sx[which][0];
    __half* dl = isW ? g_sw[which][1] : g_sx[which][1];
    int i = blockIdx.x * 256 + threadIdx.x;
    if (i >= n4) return;
    float4 x = ((const float4*)src)[i];
    __half h[4], l[4];
    split2(x.x, h[0], l[0]);
    split2(x.y, h[1], l[1]);
    split2(x.z, h[2], l[2]);
    split2(x.w, h[3], l[3]);
    ((uint2*)dh)[i] = *(uint2*)h;
    ((uint2*)dl)[i] = *(uint2*)l;
}

// ---------------- mma.sync projection GEMM (round-11 config: 8 warps) -----
// fp16 2-split, 3 products (AhBh + AhBl + AlBh) into ONE accumulator.
#define BM 128
#define BN 128
#define BK 32
#define SROW 40
#define TILE_H (BM * SROW)
#define PROJ_SMEM (2 * 4 * TILE_H * 2)

__device__ __forceinline__ uint32_t smem_u32(const void* p) {
    uint32_t a;
    asm("{ .reg .u64 t; cvta.to.shared.u64 t, %1; cvt.u32.u64 %0, t; }" : "=r"(a) : "l"(p));
    return a;
}
__device__ __forceinline__ void cpa16(uint32_t dst, const void* src) {
    asm volatile("cp.async.cg.shared.global [%0], [%1], 16;" :: "r"(dst), "l"(src));
}
__device__ __forceinline__ void ldsm_x4(uint32_t& r0, uint32_t& r1, uint32_t& r2, uint32_t& r3, uint32_t a) {
    asm volatile("ldmatrix.sync.aligned.m8n8.x4.shared.b16 {%0,%1,%2,%3}, [%4];"
        : "=r"(r0), "=r"(r1), "=r"(r2), "=r"(r3) : "r"(a));
}
__device__ __forceinline__ void ldsm_x2(uint32_t& r0, uint32_t& r1, uint32_t a) {
    asm volatile("ldmatrix.sync.aligned.m8n8.x2.shared.b16 {%0,%1}, [%2];"
        : "=r"(r0), "=r"(r1) : "r"(a));
}
__device__ __forceinline__ void mma16816(float* c, const uint32_t* a, const uint32_t* b) {
    asm volatile("mma.sync.aligned.m16n8k16.row.col.f32.f16.f16.f32 "
        "{%0,%1,%2,%3}, {%4,%5,%6,%7}, {%8,%9}, {%0,%1,%2,%3};"
        : "+f"(c[0]), "+f"(c[1]), "+f"(c[2]), "+f"(c[3])
        : "r"(a[0]), "r"(a[1]), "r"(a[2]), "r"(a[3]), "r"(b[0]), "r"(b[1]));
}

__global__ __launch_bounds__(256) void proj_mma(
    int zbase,
    const float* __restrict__ bq, const float* __restrict__ bk, const float* __restrict__ bv)
{
    extern __shared__ __half dsm[];

    int z = blockIdx.z + zbase;
    int m0 = blockIdx.x * BM;
    int n0 = blockIdx.y * BN;
    int tid = threadIdx.x;
    int lane = tid & 31, wid = tid >> 5;
    int warp_m = wid & 1;
    int warp_n = wid >> 1;

    const int nch = EE / BK;   // 16

    const float* bias = (z == 0) ? bq : (z == 1) ? bk : bv;
    float* out = (z == 0) ? g_q : (z == 1) ? g_k : g_v;

    uint32_t sbase = smem_u32(dsm);

    float acc[4][4][4];
    #pragma unroll
    for (int i = 0; i < 4; i++)
        #pragma unroll
        for (int j = 0; j < 4; j++)
            #pragma unroll
            for (int c = 0; c < 4; c++) acc[i][j][c] = 0.f;

    int vrow0 = tid >> 2,         vcc0 = tid & 3;
    int vrow1 = (tid + 256) >> 2, vcc1 = (tid + 256) & 3;

    auto issue_load = [&](int c, int buf) {
        int k0 = c * BK;
        const __half* srcs[4] = {
            g_sx[z][0] + (size_t)m0 * EE + k0,
            g_sx[z][1] + (size_t)m0 * EE + k0,
            g_sw[z][0] + (size_t)n0 * EE + k0,
            g_sw[z][1] + (size_t)n0 * EE + k0
        };
        #pragma unroll
        for (int which = 0; which < 4; which++) {
            uint32_t db = sbase + (uint32_t)(buf * 4 + which) * TILE_H * 2;
            cpa16(db + (vrow0 * SROW + vcc0 * 8) * 2, srcs[which] + (size_t)vrow0 * EE + vcc0 * 8);
            cpa16(db + (vrow1 * SROW + vcc1 * 8) * 2, srcs[which] + (size_t)vrow1 * EE + vcc1 * 8);
        }
        asm volatile("cp.async.commit_group;" ::: "memory");
    };

    issue_load(0, 0);

    for (int c = 0; c < nch; c++) {
        int buf = c & 1;
        if (c + 1 < nch) {
            issue_load(c + 1, buf ^ 1);
            asm volatile("cp.async.wait_group 1;" ::: "memory");
        } else {
            asm volatile("cp.async.wait_group 0;" ::: "memory");
        }
        __syncthreads();

        uint32_t Ah = sbase + (uint32_t)(buf * 4 + 0) * TILE_H * 2;
        uint32_t Al = sbase + (uint32_t)(buf * 4 + 1) * TILE_H * 2;
        uint32_t Bh = sbase + (uint32_t)(buf * 4 + 2) * TILE_H * 2;
        uint32_t Bl = sbase + (uint32_t)(buf * 4 + 3) * TILE_H * 2;

        #pragma unroll
        for (int ks = 0; ks < 2; ks++) {
            uint32_t bhf[4][2], blf[4][2];
            int khb = ks * 16 + ((lane >> 3) & 1) * 8;
            #pragma unroll
            for (int nt = 0; nt < 4; nt++) {
                int r = warp_n * 32 + nt * 8 + (lane & 7);
                ldsm_x2(bhf[nt][0], bhf[nt][1], Bh + (r * SROW + khb) * 2);
                ldsm_x2(blf[nt][0], blf[nt][1], Bl + (r * SROW + khb) * 2);
            }
            int kha = ks * 16 + (lane >> 4) * 8;
            #pragma unroll
            for (int mt = 0; mt < 4; mt++) {
                int r = warp_m * 64 + mt * 16 + (lane & 15);
                uint32_t ahf[4], alf[4];
                ldsm_x4(ahf[0], ahf[1], ahf[2], ahf[3], Ah + (r * SROW + kha) * 2);
                ldsm_x4(alf[0], alf[1], alf[2], alf[3], Al + (r * SROW + kha) * 2);
                #pragma unroll
                for (int nt = 0; nt < 4; nt++) {
                    mma16816(acc[mt][nt], ahf, bhf[nt]);
                    mma16816(acc[mt][nt], ahf, blf[nt]);
                    mma16816(acc[mt][nt], alf, bhf[nt]);
                }
            }
        }
        __syncthreads();
    }

    int gpr = lane >> 2, tg = lane & 3;
    #pragma unroll
    for (int mt = 0; mt < 4; mt++) {
        #pragma unroll
        for (int nt = 0; nt < 4; nt++) {
            int m = m0 + warp_m * 64 + mt * 16 + gpr;
            int n = n0 + warp_n * 32 + nt * 8 + tg * 2;
            float b0v = bias[n], b1v = bias[n + 1];
            int h = n >> 6, d = n & 63;
            {
                int bb = m >> 11, l = m & 2047;
                float2 o = { acc[mt][nt][0] + b0v, acc[mt][nt][1] + b1v };
                *(float2*)&out[(((size_t)bb * HH + h) * LL + l) * DD + d] = o;
            }
            {
                int m2 = m + 8;
                int bb = m2 >> 11, l = m2 & 2047;
                float2 o = { acc[mt][nt][2] + b0v, acc[mt][nt][3] + b1v };
                *(float2*)&out[(((size_t)bb * HH + h) * LL + l) * DD + d] = o;
            }
        }
    }
}

// ---------------- qk_sample ----------------
__global__ __launch_bounds__(256) void qk_sample_kernel(const int* __restrict__ idxs) {
    __shared__ int sidx[32 * UU];
    int t = threadIdx.x;
    int gw0 = blockIdx.x * 32;
    int bh = gw0 >> 11;
    int lbase = gw0 & 2047;

    #pragma unroll
    for (int i = t; i < 32 * UU; i += 256)
        sidx[i] = idxs[lbase * UU + i];
    __syncthreads();

    int w = t >> 5, lane = t & 31;
    int grp = lane >> 3, lid = lane & 7;
    int lix = w * 4 + grp;
    int l = lbase + lix;

    const float* qrow = g_q + ((size_t)bh * LL + l) * DD;
    float4 q0 = *(const float4*)&qrow[lid * 8];
    float4 q1 = *(const float4*)&qrow[lid * 8 + 4];
    const float* kbase = g_k + (size_t)bh * LL * DD;

    float smax = -FLT_MAX, ssum = 0.f;
    #pragma unroll 2
    for (int s = 0; s < UU; s += 2) {
        int ki0 = sidx[lix * UU + s];
        int ki1 = sidx[lix * UU + s + 1];
        const float* kr0 = &kbase[(size_t)ki0 * DD + lid * 8];
        const float* kr1 = &kbase[(size_t)ki1 * DD + lid * 8];
        float4 a0 = *(const float4*)kr0;
        float4 a1 = *(const float4*)(kr0 + 4);
        float4 b0 = *(const float4*)kr1;
        float4 b1 = *(const float4*)(kr1 + 4);
        float p0 = q0.x*a0.x + q0.y*a0.y + q0.z*a0.z + q0.w*a0.w
                 + q1.x*a1.x + q1.y*a1.y + q1.z*a1.z + q1.w*a1.w;
        float p1 = q0.x*b0.x + q0.y*b0.y + q0.z*b0.z + q0.w*b0.w
                 + q1.x*b1.x + q1.y*b1.y + q1.z*b1.z + q1.w*b1.w;
        #pragma unroll
        for (int off = 4; off; off >>= 1) {
            p0 += __shfl_xor_sync(0xffffffffu, p0, off);
            p1 += __shfl_xor_sync(0xffffffffu, p1, off);
        }
        smax = fmaxf(smax, fmaxf(p0, p1));
        ssum += p0 + p1;
    }
    if (lid == 0) g_M[gw0 + lix] = smax - ssum * (1.0f / LL);
}

// ---------------- topk via bitonic sort ----------------
__device__ __forceinline__ unsigned long long pack_key(float v, int idx) {
    uint32_t s = __float_as_uint(v);
    s = (s & 0x80000000u) ? ~s : (s | 0x80000000u);
    return ((unsigned long long)s << 32) | (unsigned long long)(0xFFFFFFFFu - (uint32_t)idx);
}

__global__ __launch_bounds__(256) void topk1_kernel() {
    __shared__ unsigned long long keys[256];
    int bh = blockIdx.x, ch = blockIdx.y, t = threadIdx.x;
    int gidx = ch * 256 + t;
    keys[t] = pack_key(g_M[bh * LL + gidx], gidx);
    __syncthreads();
    for (int k = 2; k <= 256; k <<= 1) {
        for (int j = k >> 1; j > 0; j >>= 1) {
            int ixj = t ^ j;
            unsigned long long a = keys[t], b = keys[ixj];
            bool desc = ((t & k) == 0);
            unsigned long long mx = (a > b) ? a : b;
            unsigned long long mn = (a > b) ? b : a;
            unsigned long long nv = (((t < ixj) == desc) ? mx : mn);
            __syncthreads();
            keys[t] = nv;
            __syncthreads();
        }
    }
    if (t < NTOP) g_cand[(bh * 8 + ch) * NTOP + t] = keys[t];
}

__global__ __launch_bounds__(512) void topk2_kernel() {
    __shared__ unsigned long long keys[512];
    int bh = blockIdx.x, t = threadIdx.x;
    keys[t] = (t < 8 * NTOP) ? g_cand[bh * 8 * NTOP + t] : 0ull;
    __syncthreads();
    for (int k = 2; k <= 512; k <<= 1) {
        for (int j = k >> 1; j > 0; j >>= 1) {
            int ixj = t ^ j;
            unsigned long long a = keys[t], b = keys[ixj];
            bool desc = ((t & k) == 0);
            unsigned long long mx = (a > b) ? a : b;
            unsigned long long mn = (a > b) ? b : a;
            unsigned long long nv = (((t < ixj) == desc) ? mx : mn);
            __syncthreads();
            keys[t] = nv;
            __syncthreads();
        }
    }
    if (t < NTOP)
        g_top[bh * NTOP + t] = (int)(0xFFFFFFFFu - (uint32_t)(keys[t] & 0xFFFFFFFFu));
}

// ---------------- fused scores+exp+den+upd ----------------
__global__ __launch_bounds__(256) void attn_fused() {
    __shared__ float qs[NTOP * DD];
    __shared__ float kst[DD][AST + 1];
    __shared__ float vs[AST * DD];
    __shared__ float es[NTOP][AST];

    int bh = blockIdx.x, ch = blockIdx.y;
    int t = threadIdx.x;
    int lane = t & 31, w = t >> 5;
    int d = t & 63, gq = t >> 6;

    for (int i = t; i < NTOP * DD; i += 256) {
        int u = i >> 6, dd = i & 63;
        int l = g_top[bh * NTOP + u];
        qs[i] = g_q[((size_t)bh * LL + l) * DD + dd];
    }

    float den_acc[5] = {0.f, 0.f, 0.f, 0.f, 0.f};
    float upd_acc[10] = {0.f,0.f,0.f,0.f,0.f,0.f,0.f,0.f,0.f,0.f};

    for (int st = 0; st < ALT / AST; st++) {
        int l0 = ch * ALT + st * AST;
        __syncthreads();
        for (int i = t; i < AST * DD; i += 256) {
            int ln = i >> 6, dd = i & 63;
            kst[dd][ln] = g_k[((size_t)bh * LL + l0 + ln) * DD + dd];
        }
        for (int i = t; i < AST * DD; i += 256)
            vs[i] = g_v[((size_t)bh * LL + l0) * DD + i];
        __syncthreads();

        float sc[5] = {0.f, 0.f, 0.f, 0.f, 0.f};
        #pragma unroll 8
        for (int kk = 0; kk < DD; kk++) {
            float kv = kst[kk][lane];
            #pragma unroll
            for (int g = 0; g < 5; g++)
                sc[g] += qs[(g * 8 + w) * DD + kk] * kv;
        }
        #pragma unroll
        for (int g = 0; g < 5; g++) {
            float e = expf(sc[g]);
            es[g * 8 + w][lane] = e;
            den_acc[g] += e;
        }
        __syncthreads();

        #pragma unroll 8
        for (int ln = 0; ln < AST; ln++) {
            float vv = vs[ln * DD + d];
            #pragma unroll
            for (int j = 0; j < 10; j++)
                upd_acc[j] += es[gq * 10 + j][ln] * vv;
        }
    }

    #pragma unroll
    for (int j = 0; j < 10; j++) {
        int u = gq * 10 + j;
        g_pupd[(((size_t)ch * BH + bh) * NTOP + u) * DD + d] = upd_acc[j];
    }
    #pragma unroll
    for (int g = 0; g < 5; g++) {
        float v = den_acc[g];
        #pragma unroll
        for (int off = 16; off; off >>= 1) v += __shfl_xor_sync(0xffffffffu, v, off);
        if (lane == 0) g_pden[(ch * BH + bh) * NTOP + g * 8 + w] = v;
    }
}

__global__ __launch_bounds__(256) void vmean_kernel() {
    __shared__ float sm[256];
    int bh = blockIdx.x, t = threadIdx.x;
    int d = t & 63, p = t >> 6;
    float s = 0.f;
    for (int l = p; l < LL; l += 4) s += g_v[((size_t)bh * LL + l) * DD + d];
    sm[t] = s; __syncthreads();
    if (t < 128) sm[t] += sm[t + 128];
    __syncthreads();
    if (t < 64) g_vmean[bh * DD + t] = (sm[t] + sm[t + 64]) * (1.0f / LL);
}

__global__ __launch_bounds__(128) void base_kernel(const float* __restrict__ Wo,
                                                   const float* __restrict__ bo) {
    __shared__ float cm[EE];
    int b = blockIdx.x, jc = blockIdx.y, t = threadIdx.x;
    for (int i = t; i < EE; i += 128) cm[i] = g_vmean[b * EE + i];
    __syncthreads();
    int j = jc * 128 + t;
    float acc = bo[j];
    const float* wrow = Wo + (size_t)j * EE;
    for (int e = 0; e < EE; e += 4) {
        float4 w = *(const float4*)&wrow[e];
        acc += cm[e] * w.x + cm[e+1] * w.y + cm[e+2] * w.z + cm[e+3] * w.w;
    }
    g_base[b * EE + j] = acc;
}

__global__ __launch_bounds__(256) void fill_kernel(float4* __restrict__ out4) {
    int i = blockIdx.x * 256 + threadIdx.x;
    int b  = i >> 18;
    int j4 = i & 127;
    out4[i] = *(const float4*)&g_base[b * EE + j4 * 4];
}

// ---------------- fused updreduce + sparse row update ----------------
__global__ __launch_bounds__(512) void update_kernel(const float* __restrict__ Wo,
                                                     float* __restrict__ out) {
    __shared__ float del[DD];
    int r = blockIdx.x;
    int bh = r / NTOP, u = r - bh * NTOP;
    int b = bh >> 3, h = bh & 7;
    int t = threadIdx.x;
    if (t < DD) {
        float s = 0.f, den = 0.f;
        #pragma unroll
        for (int c = 0; c < ACH; c++) {
            s   += g_pupd[(((size_t)c * BH + bh) * NTOP + u) * DD + t];
            den += g_pden[(c * BH + bh) * NTOP + u];
        }
        del[t] = s / den - g_vmean[bh * DD + t];
    }
    __syncthreads();
    int l = g_top[r];
    const float* wrow = Wo + (size_t)t * EE + h * DD;
    float acc = 0.f;
    #pragma unroll
    for (int dd = 0; dd < DD; dd += 4) {
        float4 w = *(const float4*)&wrow[dd];
        acc += del[dd] * w.x + del[dd+1] * w.y + del[dd+2] * w.z + del[dd+3] * w.w;
    }
    atomicAdd(&out[((size_t)b * LL + l) * EE + t], acc);
}

extern "C" void kernel_launch(void* const* d_in, const int* in_sizes, int n_in,
                              void* d_out, int out_size) {
    const float* query = (const float*)d_in[0];
    const float* key   = (const float*)d_in[1];
    const float* value = (const float*)d_in[2];
    const int*   idxs  = (const int*)d_in[3];
    const float* Wq = (const float*)d_in[4];
    const float* bq = (const float*)d_in[5];
    const float* Wk = (const float*)d_in[6];
    const float* bk = (const float*)d_in[7];
    const float* Wv = (const float*)d_in[8];
    const float* bv = (const float*)d_in[9];
    const float* Wo = (const float*)d_in[10];
    const float* bo = (const float*)d_in[11];
    float* out = (float*)d_out;

    static cudaStream_t s2 = nullptr;
    static cudaEvent_t eSplit = nullptr, eV = nullptr, eFill = nullptr;
    if (s2 == nullptr) {
        cudaStreamCreateWithFlags(&s2, cudaStreamNonBlocking);
        cudaEventCreateWithFlags(&eSplit, cudaEventDisableTiming);
        cudaEventCreateWithFlags(&eV, cudaEventDisableTiming);
        cudaEventCreateWithFlags(&eFill, cudaEventDisableTiming);
    }

    cudaFuncSetAttribute(proj_mma, cudaFuncAttributeMaxDynamicSharedMemorySize, PROJ_SMEM);

    const int ACT_N4 = NROWS * EE / 4;   // 1,048,576 -> 4096 blocks
    const int W_N4   = EE * EE / 4;      // 65,536    -> 256 blocks

    // ---- main stream: q,k activation splits + all weight splits, then q,k proj ----
    split_kernel<<<dim3(ACT_N4 / 256, 2), 256>>>(query, key, value, ACT_N4, 0, 0);   // q,k acts
    split_kernel<<<dim3(W_N4 / 256, 3), 256>>>(Wq, Wk, Wv, W_N4, 1, 0);              // weights
    cudaEventRecord(eSplit, 0);

    proj_mma<<<dim3(NROWS / BM, EE / BN, 2), 256, PROJ_SMEM>>>(0, bq, bk, bv);       // q, k

    // ---- side stream: v act split, v projection, vmean, base, fill ----
    cudaStreamWaitEvent(s2, eSplit, 0);
    split_kernel<<<dim3(ACT_N4 / 256, 1), 256, 0, s2>>>(query, key, value, ACT_N4, 0, 2);  // v acts
    proj_mma<<<dim3(NROWS / BM, EE / BN, 1), 256, PROJ_SMEM, s2>>>(2, bq, bk, bv);   // v
    cudaEventRecord(eV, s2);
    vmean_kernel<<<BH, 256, 0, s2>>>();
    base_kernel<<<dim3(BB, 4), 128, 0, s2>>>(Wo, bo);
    fill_kernel<<<4096, 256, 0, s2>>>((float4*)out);
    cudaEventRecord(eFill, s2);

    // ---- main stream: qk -> topk -> attn -> update ----
    qk_sample_kernel<<<BH * LL / 32, 256>>>(idxs);
    topk1_kernel<<<dim3(BH, 8), 256>>>();
    topk2_kernel<<<BH, 512>>>();
    cudaStreamWaitEvent(0, eV, 0);
    attn_fused<<<dim3(BH, ACH), 256>>>();
    cudaStreamWaitEvent(0, eFill, 0);
    update_kernel<<<BH * NTOP, 512>>>(Wo, out);
}